// round 3
// baseline (speedup 1.0000x reference)
#include <cuda_runtime.h>
#include <cstdint>

#define KCLS   128
#define DDIM   64
#define BROWS  256
#define NTH    512
#define NWARP  16
#define GRID_MAIN 304

// dynamic smem layout (bytes)
#define OFF_ACC   0          // float2 acc[KCLS*32]        : 32768
#define OFF_ACC2  32768      // float  acc2[KCLS*32]       : 16384
#define OFF_CNT   49152      // float  scnt[KCLS]          : 512
#define OFF_LAB   49664      // int    slab[BROWS]         : 1024
#define OFF_WL    50688      // int    wlist[NWARP*256]    : 16384
#define SMEM_MAIN 67072

__device__ float g_sums[KCLS * DDIM];
__device__ float g_cnt[KCLS];
__device__ float g_ssq[KCLS];

// ---------------- zero pass ----------------
__global__ void k_zero() {
    int t = blockIdx.x * blockDim.x + threadIdx.x;
    int stride = gridDim.x * blockDim.x;
    for (int i = t; i < KCLS * DDIM; i += stride) g_sums[i] = 0.f;
    if (t < KCLS) { g_cnt[t] = 0.f; g_ssq[t] = 0.f; }
}

// ---------------- main accumulation ----------------
__global__ void __launch_bounds__(NTH, 2)
k_main(const float2* __restrict__ z2, const int* __restrict__ labels,
       long long nrows) {
    extern __shared__ char sm[];
    float2* acc  = (float2*)(sm + OFF_ACC);
    float*  acc2 = (float*) (sm + OFF_ACC2);
    float*  scnt = (float*) (sm + OFF_CNT);
    int*    slab = (int*)   (sm + OFF_LAB);
    int*    wlist= (int*)   (sm + OFF_WL);

    const int tid  = threadIdx.x;
    const int warp = tid >> 5;
    const int lane = tid & 31;
    int* wl = wlist + warp * 256;

    // zero private accumulators
    for (int i = tid; i < KCLS * 32; i += NTH) {
        acc[i]  = make_float2(0.f, 0.f);
        acc2[i] = 0.f;
    }
    if (tid < KCLS) scnt[tid] = 0.f;

    const long long nb = (nrows + BROWS - 1) / BROWS;
    long long tile = blockIdx.x;

    // prefetch labels for first tile into a register
    int plab = -1;
    if (tile < nb && tid < BROWS) {
        long long r = tile * BROWS + tid;
        if (r < nrows) {
            int L = labels[r];
            plab = (L >= 0 && L < KCLS) ? L : -1;
        }
    }
    __syncthreads();

    for (; tile < nb; tile += gridDim.x) {
        if (tid < BROWS) slab[tid] = plab;
        __syncthreads();

        // prefetch labels for the next tile (LDG latency hides behind processing)
        plab = -1;
        {
            long long nt = tile + gridDim.x;
            if (nt < nb && tid < BROWS) {
                long long r = nt * BROWS + tid;
                if (r < nrows) {
                    int L = labels[r];
                    plab = (L >= 0 && L < KCLS) ? L : -1;
                }
            }
        }

        // ---- scan: build this warp's worklist ----
        int m = 0;
        #pragma unroll
        for (int base = 0; base < BROWS; base += 32) {
            int lab = slab[base + lane];
            bool mine = (lab >= 0) && ((lab >> 3) == warp);
            unsigned msk = __ballot_sync(0xffffffffu, mine);
            if (mine) {
                int rank = __popc(msk & ((1u << lane) - 1));
                wl[m + rank] = ((base + lane) << 8) | lab;
            }
            m += __popc(msk);
        }
        __syncwarp();

        // ---- process matches with depth-4 LDG pipeline ----
        const long long rowbase = tile * BROWS;
        float2 q0, q1, q2, q3;
        int e0 = 0, e1 = 0, e2 = 0, e3 = 0;

#define FETCH(s, idx) do { if ((idx) < m) { e##s = wl[(idx)]; \
        q##s = z2[(rowbase + (long long)(e##s >> 8)) * 32 + lane]; } } while (0)
#define CONSUME(s) do { if (i + s < m) { \
        int kk = e##s & 255; \
        float2 t = acc[kk * 32 + lane]; \
        t.x += q##s.x; t.y += q##s.y; \
        acc[kk * 32 + lane] = t; \
        acc2[kk * 32 + lane] += q##s.x * q##s.x + q##s.y * q##s.y; \
        if (lane == 0) scnt[kk] += 1.f; \
        FETCH(s, i + 4 + s); } } while (0)

        FETCH(0, 0); FETCH(1, 1); FETCH(2, 2); FETCH(3, 3);
        for (int i = 0; i < m; i += 4) {
            CONSUME(0); CONSUME(1); CONSUME(2); CONSUME(3);
        }
#undef FETCH
#undef CONSUME
        __syncthreads();
    }

    // ---- flush CTA partials to global ----
    __syncthreads();
    for (int idx = tid; idx < KCLS * 32; idx += NTH) {
        float2 v = acc[idx];
        atomicAdd(&g_sums[idx * 2 + 0], v.x);
        atomicAdd(&g_sums[idx * 2 + 1], v.y);
    }
    if (tid < KCLS) {
        float s = 0.f;
        #pragma unroll
        for (int l = 0; l < 32; l++) s += acc2[tid * 32 + l];
        atomicAdd(&g_ssq[tid], s);
        atomicAdd(&g_cnt[tid], scnt[tid]);
    }
}

// ---------------- finalize: centers, intra, pairwise inter, loss ----------------
__global__ void __launch_bounds__(512) k_final(float* out) {
    __shared__ float c[KCLS * 65];      // padded to kill bank conflicts
    __shared__ float sqn[KCLS];
    __shared__ float varr[KCLS];
    __shared__ float cntk[KCLS];
    __shared__ float rsum[512];
    __shared__ float rcnt[512];

    int t = threadIdx.x;
    if (t < KCLS) cntk[t] = g_cnt[t];
    __syncthreads();

    for (int idx = t; idx < KCLS * DDIM; idx += 512) {
        int k = idx >> 6, d = idx & 63;
        float safe = fmaxf(cntk[k], 1.f);
        c[k * 65 + d] = g_sums[idx] / safe;
    }
    __syncthreads();

    if (t < KCLS) {
        float s = 0.f;
        #pragma unroll
        for (int d = 0; d < DDIM; d++) {
            float v = c[t * 65 + d];
            s = fmaf(v, v, s);
        }
        sqn[t] = s;
        float safe = fmaxf(cntk[t], 1.f);
        varr[t] = g_ssq[t] / safe - s;
    }
    __syncthreads();

    float dsum = 0.f, pcnt = 0.f;
    for (int p = t; p < KCLS * KCLS; p += 512) {
        int i = p >> 7, j = p & 127;
        if (j > i && cntk[i] > 0.f && cntk[j] > 0.f) {
            float d0 = 0.f, d1 = 0.f;
            #pragma unroll
            for (int d = 0; d < DDIM; d += 2) {
                d0 = fmaf(c[i * 65 + d],     c[j * 65 + d],     d0);
                d1 = fmaf(c[i * 65 + d + 1], c[j * 65 + d + 1], d1);
            }
            float sq = sqn[i] + sqn[j] - 2.f * (d0 + d1);
            dsum += sqrtf(fmaxf(sq, 0.f));
            pcnt += 1.f;
        }
    }
    rsum[t] = dsum; rcnt[t] = pcnt;
    __syncthreads();
    for (int s2 = 256; s2 > 0; s2 >>= 1) {
        if (t < s2) { rsum[t] += rsum[t + s2]; rcnt[t] += rcnt[t + s2]; }
        __syncthreads();
    }

    if (t == 0) {
        float ivar = 0.f;
        int nh2 = 0, nv = 0;
        for (int k = 0; k < KCLS; k++) {
            if (cntk[k] > 1.f) { ivar += varr[k]; nh2++; }
            if (cntk[k] > 0.f) nv++;
        }
        float intra = (nh2 > 0) ? ivar / (float)nh2 : 0.f;
        float inter = (rcnt[0] > 0.f) ? -rsum[0] / rcnt[0] : 0.f;
        float loss = intra + 0.5f * inter;
        out[0] = (nv >= 2) ? loss : 0.f;
    }
}

// ---------------- launch ----------------
extern "C" void kernel_launch(void* const* d_in, const int* in_sizes, int n_in,
                              void* d_out, int out_size) {
    const float2* z2 = (const float2*)d_in[0];
    const int* labels = (const int*)d_in[1];
    long long nrows = (long long)in_sizes[0] / DDIM;

    cudaFuncSetAttribute(k_main, cudaFuncAttributeMaxDynamicSharedMemorySize,
                         SMEM_MAIN);

    k_zero<<<32, 256>>>();
    k_main<<<GRID_MAIN, NTH, SMEM_MAIN>>>(z2, labels, nrows);
    k_final<<<1, 512>>>((float*)d_out);
}

// round 4
// speedup vs baseline: 1.4379x; 1.4379x over previous
#include <cuda_runtime.h>

#define KCLS   128
#define DDIM   64
#define BROWS  256
#define NTH    512
#define NWARP  16
#define GRID_MAIN 304
#define PART_STRIDE 8448        // 8192 sums + 128 cnt + 128 ssq
#define PAIRBLKS 16

// dynamic smem layout for k_main (bytes)
#define OFF_ACC   0             // float2 acc[KCLS*32] : 32768
#define OFF_ACC2  32768         // float  acc2[KCLS*32]: 16384
#define OFF_CNT   49152         // float  scnt[KCLS]   : 512
#define OFF_WL    49664         // int    wl[16*256]   : 16384
#define SMEM_MAIN 66048

__device__ float g_part[GRID_MAIN * PART_STRIDE];   // per-CTA partials (overwritten fully)
__device__ float g_centers[KCLS * DDIM];
__device__ float g_sqn[KCLS];
__device__ float g_cntk[KCLS];
__device__ float g_ivar, g_nh2, g_nvalid, g_dsum, g_pcnt;
__device__ unsigned g_ticket;

// ================= main accumulation: no barriers in the hot loop =================
__global__ void __launch_bounds__(NTH, 2)
k_main(const float2* __restrict__ z2, const int* __restrict__ labels, int nrows) {
    extern __shared__ char sm[];
    float2* acc  = (float2*)(sm + OFF_ACC);
    float*  acc2 = (float*) (sm + OFF_ACC2);
    float*  scnt = (float*) (sm + OFF_CNT);
    int*    wlist= (int*)   (sm + OFF_WL);

    const int tid  = threadIdx.x;
    const int warp = tid >> 5;
    const int lane = tid & 31;
    int* wl = wlist + warp * 256;

    if (blockIdx.x == 0 && tid == 0) {
        g_ivar = 0.f; g_nh2 = 0.f; g_nvalid = 0.f;
        g_dsum = 0.f; g_pcnt = 0.f; g_ticket = 0u;
    }

    // zero CTA-private accumulators
    for (int i = tid; i < KCLS * 32; i += NTH) {
        acc[i]  = make_float2(0.f, 0.f);
        acc2[i] = 0.f;
    }
    if (tid < KCLS) scnt[tid] = 0.f;
    __syncthreads();   // last CTA-wide sync until flush

    const int nb = (nrows + BROWS - 1) / BROWS;

    // per-warp register prefetch of this warp's first tile labels
    int plab[8];
    int tile = blockIdx.x;
    #pragma unroll
    for (int g = 0; g < 8; g++) {
        int r = tile * BROWS + g * 32 + lane;
        plab[g] = (tile < nb && r < nrows) ? labels[r] : -1;
    }

    for (; tile < nb; tile += GRID_MAIN) {
        __syncwarp();
        int cur[8];
        #pragma unroll
        for (int g = 0; g < 8; g++) cur[g] = plab[g];

        // prefetch next tile's labels (latency hidden behind scan+consume)
        {
            int nt = tile + GRID_MAIN;
            #pragma unroll
            for (int g = 0; g < 8; g++) {
                int r = nt * BROWS + g * 32 + lane;
                plab[g] = (nt < nb && r < nrows) ? labels[r] : -1;
            }
        }

        // ---- scan: build this warp's worklist from registers ----
        int m = 0;
        #pragma unroll
        for (int g = 0; g < 8; g++) {
            int lab = cur[g];
            bool mine = ((unsigned)lab < 128u) && ((lab >> 3) == warp);
            unsigned msk = __ballot_sync(0xffffffffu, mine);
            if (mine) {
                int rank = __popc(msk & ((1u << lane) - 1));
                wl[m + rank] = ((g * 32 + lane) << 8) | lab;
            }
            m += __popc(msk);
        }
        __syncwarp();

        // ---- consume matches with depth-4 LDG pipeline ----
        const int rowbase = tile * BROWS;
        float2 q0, q1, q2, q3;
        int e0 = 0, e1 = 0, e2 = 0, e3 = 0;

#define FETCH(s, idx) do { if ((idx) < m) { e##s = wl[(idx)]; \
        q##s = z2[(rowbase + (e##s >> 8)) * 32 + lane]; } } while (0)
#define CONSUME(s) do { if (i + s < m) { \
        int kk = e##s & 255; \
        float2 t = acc[kk * 32 + lane]; \
        t.x += q##s.x; t.y += q##s.y; \
        acc[kk * 32 + lane] = t; \
        acc2[kk * 32 + lane] += q##s.x * q##s.x + q##s.y * q##s.y; \
        if (lane == 0) scnt[kk] += 1.f; \
        FETCH(s, i + 4 + s); } } while (0)

        FETCH(0, 0); FETCH(1, 1); FETCH(2, 2); FETCH(3, 3);
        for (int i = 0; i < m; i += 4) {
            CONSUME(0); CONSUME(1); CONSUME(2); CONSUME(3);
        }
#undef FETCH
#undef CONSUME
    }

    // ---- flush CTA partials (no atomics, no init needed) ----
    __syncthreads();
    float* P = g_part + blockIdx.x * PART_STRIDE;
    float2* P2 = (float2*)P;
    for (int idx = tid; idx < KCLS * 32; idx += NTH)
        P2[idx] = acc[idx];              // [k][d] layout matches acc layout exactly
    if (tid < KCLS) {
        float s = 0.f;
        #pragma unroll
        for (int l = 0; l < 32; l++) s += acc2[tid * 32 + l];
        P[8192 + tid] = scnt[tid];
        P[8320 + tid] = s;
    }
}

// ================= per-class reduction: centers, sqn, var, intra scalars =================
__global__ void __launch_bounds__(256) k_mid() {
    const int k = blockIdx.x;
    const int t = threadIdx.x;
    __shared__ float sred[256];
    __shared__ float wcn[8], wsq[8];
    __shared__ float sc[2];
    __shared__ float sq2r[2];

    // dim sums: 4 groups of 64 threads stride over the 304 CTAs
    const int d = t & 63, g = t >> 6;
    float s = 0.f;
    for (int c = g; c < GRID_MAIN; c += 4)
        s += g_part[c * PART_STRIDE + k * 64 + d];
    sred[t] = s;

    // cnt / ssq partials
    float cn = 0.f, sq = 0.f;
    for (int c = t; c < GRID_MAIN; c += 256) {
        cn += g_part[c * PART_STRIDE + 8192 + k];
        sq += g_part[c * PART_STRIDE + 8320 + k];
    }
    #pragma unroll
    for (int o = 16; o; o >>= 1) {
        cn += __shfl_down_sync(0xffffffffu, cn, o);
        sq += __shfl_down_sync(0xffffffffu, sq, o);
    }
    if ((t & 31) == 0) { wcn[t >> 5] = cn; wsq[t >> 5] = sq; }
    __syncthreads();

    if (t == 0) {
        float c0 = 0.f, s0 = 0.f;
        #pragma unroll
        for (int w = 0; w < 8; w++) { c0 += wcn[w]; s0 += wsq[w]; }
        sc[0] = c0; sc[1] = s0;
    }
    __syncthreads();

    const float cnt = sc[0], ssq = sc[1];
    const float safe = fmaxf(cnt, 1.f);

    float sq2 = 0.f;
    if (t < 64) {
        float sum = sred[t] + sred[t + 64] + sred[t + 128] + sred[t + 192];
        float cd = sum / safe;
        g_centers[k * 64 + t] = cd;
        sq2 = cd * cd;
    }
    #pragma unroll
    for (int o = 16; o; o >>= 1) sq2 += __shfl_down_sync(0xffffffffu, sq2, o);
    if (t == 0)  sq2r[0] = sq2;
    if (t == 32) sq2r[1] = sq2;
    __syncthreads();

    if (t == 0) {
        float sqn = sq2r[0] + sq2r[1];
        g_sqn[k] = sqn;
        g_cntk[k] = cnt;
        float var = ssq / safe - sqn;
        if (cnt > 1.f) { atomicAdd(&g_ivar, var); atomicAdd(&g_nh2, 1.f); }
        if (cnt > 0.f) atomicAdd(&g_nvalid, 1.f);
    }
}

// ================= pairwise inter-center distances + final loss =================
__global__ void __launch_bounds__(256) k_pair(float* __restrict__ out) {
    __shared__ float c[KCLS * 65];
    __shared__ float cnts[KCLS];
    __shared__ float sqns[KCLS];
    __shared__ float red[256];

    const int t = threadIdx.x;
    for (int idx = t; idx < KCLS * DDIM; idx += 256)
        c[(idx >> 6) * 65 + (idx & 63)] = g_centers[idx];
    if (t < KCLS) { cnts[t] = g_cntk[t]; sqns[t] = g_sqn[t]; }
    __syncthreads();

    float dsum = 0.f, pcnt = 0.f;
    for (int p = blockIdx.x * 256 + t; p < KCLS * KCLS; p += PAIRBLKS * 256) {
        int i = p >> 7, j = p & 127;
        if (j > i && cnts[i] > 0.f && cnts[j] > 0.f) {
            float d0 = 0.f, d1 = 0.f;
            #pragma unroll
            for (int d = 0; d < DDIM; d += 2) {
                d0 = fmaf(c[i * 65 + d],     c[j * 65 + d],     d0);
                d1 = fmaf(c[i * 65 + d + 1], c[j * 65 + d + 1], d1);
            }
            float sq = sqns[i] + sqns[j] - 2.f * (d0 + d1);
            dsum += sqrtf(fmaxf(sq, 0.f));
            pcnt += 1.f;
        }
    }

    red[t] = dsum; __syncthreads();
    for (int s = 128; s; s >>= 1) { if (t < s) red[t] += red[t + s]; __syncthreads(); }
    if (t == 0) atomicAdd(&g_dsum, red[0]);
    __syncthreads();
    red[t] = pcnt; __syncthreads();
    for (int s = 128; s; s >>= 1) { if (t < s) red[t] += red[t + s]; __syncthreads(); }

    if (t == 0) {
        atomicAdd(&g_pcnt, red[0]);
        __threadfence();
        unsigned tk = atomicAdd(&g_ticket, 1u);
        if (tk == PAIRBLKS - 1) {
            float nh2 = g_nh2, nvalid = g_nvalid, ivar = g_ivar;
            float dT = g_dsum, pT = g_pcnt;
            float intra = (nh2 > 0.f) ? ivar / nh2 : 0.f;
            float inter = (pT > 0.f) ? -dT / pT : 0.f;
            float loss = intra + 0.5f * inter;
            out[0] = (nvalid >= 2.f) ? loss : 0.f;
        }
    }
}

// ================= launch =================
extern "C" void kernel_launch(void* const* d_in, const int* in_sizes, int n_in,
                              void* d_out, int out_size) {
    const float2* z2 = (const float2*)d_in[0];
    const int* labels = (const int*)d_in[1];
    int nrows = in_sizes[0] / DDIM;

    cudaFuncSetAttribute(k_main, cudaFuncAttributeMaxDynamicSharedMemorySize,
                         SMEM_MAIN);

    k_main<<<GRID_MAIN, NTH, SMEM_MAIN>>>(z2, labels, nrows);
    k_mid<<<KCLS, 256>>>();
    k_pair<<<PAIRBLKS, 256>>>((float*)d_out);
}

// round 5
// speedup vs baseline: 1.6716x; 1.1625x over previous
#include <cuda_runtime.h>

#define KCLS   128
#define DDIM   64
#define BROWS  256
#define NTH    512
#define NWARP  16
#define GRID_MAIN 304
#define PART_STRIDE 8448        // 8192 sums + 128 cnt + 128 ssq
#define PAIRBLKS 16

// dynamic smem layout for k_main (bytes)
// acc4 : float4 [2][129][16]  = 66048   (per-half-warp class accumulators, +1 trash class)
// acc2 : float  [2][129][16]  = 16512   (per-lane sumsq partials)
// scnt : float  [2][130]      = 1040    (counts, padded)
// wl   : int    [16][256]     = 16384   (per-warp worklists)
#define OFF_ACC4  0
#define OFF_ACC2  66048
#define OFF_CNT   82560
#define OFF_WL    83600
#define SMEM_MAIN 99984

__device__ float g_part[GRID_MAIN * PART_STRIDE];
__device__ float g_centers[KCLS * DDIM];
__device__ float g_sqn[KCLS];
__device__ float g_cntk[KCLS];
__device__ float g_ivar, g_nh2, g_nvalid, g_dsum, g_pcnt;
__device__ unsigned g_ticket;

// ================= main accumulation =================
__global__ void __launch_bounds__(NTH, 2)
k_main(const float4* __restrict__ z4, const int* __restrict__ labels, int nrows) {
    extern __shared__ char sm[];
    float4* acc4 = (float4*)(sm + OFF_ACC4);
    float*  acc2 = (float*) (sm + OFF_ACC2);
    float*  scnt = (float*) (sm + OFF_CNT);
    int*    wlist= (int*)   (sm + OFF_WL);

    const int tid  = threadIdx.x;
    const int warp = tid >> 5;
    const int lane = tid & 31;
    const int hw   = lane >> 4;       // half-warp id (0/1)
    const int hl   = lane & 15;       // lane within half
    int* wl = wlist + warp * 256;

    if (blockIdx.x == 0 && tid == 0) {
        g_ivar = 0.f; g_nh2 = 0.f; g_nvalid = 0.f;
        g_dsum = 0.f; g_pcnt = 0.f; g_ticket = 0u;
    }

    // zero accumulators (83600 bytes = 5225 float4)
    {
        float4* p = (float4*)sm;
        const float4 z = make_float4(0.f, 0.f, 0.f, 0.f);
        for (int i = tid; i < 5225; i += NTH) p[i] = z;
    }
    __syncthreads();   // last CTA-wide sync until flush

    const int nb = (nrows + BROWS - 1) / BROWS;

    // per-warp register prefetch of first tile's labels
    int plab[8];
    int tile = blockIdx.x;
    #pragma unroll
    for (int g = 0; g < 8; g++) {
        int r = tile * BROWS + g * 32 + lane;
        plab[g] = (tile < nb && r < nrows) ? labels[r] : -1;
    }

    for (; tile < nb; tile += GRID_MAIN) {
        __syncwarp();
        int cur[8];
        #pragma unroll
        for (int g = 0; g < 8; g++) cur[g] = plab[g];

        // prefetch next tile's labels
        {
            int nt = tile + GRID_MAIN;
            #pragma unroll
            for (int g = 0; g < 8; g++) {
                int r = nt * BROWS + g * 32 + lane;
                plab[g] = (nt < nb && r < nrows) ? labels[r] : -1;
            }
        }

        // ---- scan: build this warp's worklist ----
        int m = 0;
        #pragma unroll
        for (int g = 0; g < 8; g++) {
            int lab = cur[g];
            bool mine = ((unsigned)lab < 128u) && ((lab >> 3) == warp);
            unsigned msk = __ballot_sync(0xffffffffu, mine);
            if (mine) {
                int rank = __popc(msk & ((1u << lane) - 1));
                wl[m + rank] = ((g * 32 + lane) << 8) | lab;
            }
            m += __popc(msk);
        }
        // pad to even with trash entry (row 0, class 128)
        if (lane == 0 && (m & 1)) wl[m] = 128;
        __syncwarp();
        const int P = (m + 1) >> 1;           // pairs

        // ---- consume pairs with depth-4 LDG pipeline ----
        const int rowbase = tile * BROWS;
        float4 q0, q1, q2, q3;
        int e0 = 0, e1 = 0, e2 = 0, e3 = 0;

#define FETCH(s, p) do { if ((p) < P) { e##s = wl[2 * (p) + hw]; \
        q##s = z4[(rowbase + (e##s >> 8)) * 16 + hl]; } } while (0)
#define CONSUME(s) do { if (i + s < P) { \
        int kk = e##s & 255; \
        int ai = (hw * 129 + kk) * 16 + hl; \
        float4 t = acc4[ai]; \
        t.x += q##s.x; t.y += q##s.y; t.z += q##s.z; t.w += q##s.w; \
        acc4[ai] = t; \
        float s2 = acc2[ai]; \
        s2 += q##s.x * q##s.x; s2 += q##s.y * q##s.y; \
        s2 += q##s.z * q##s.z; s2 += q##s.w * q##s.w; \
        acc2[ai] = s2; \
        if (hl == 0) scnt[hw * 130 + kk] += 1.f; \
        FETCH(s, i + 4 + s); } } while (0)

        FETCH(0, 0); FETCH(1, 1); FETCH(2, 2); FETCH(3, 3);
        for (int i = 0; i < P; i += 4) {
            CONSUME(0); CONSUME(1); CONSUME(2); CONSUME(3);
        }
#undef FETCH
#undef CONSUME
    }

    // ---- flush CTA partials (merge half-warp copies) ----
    __syncthreads();
    float* Pp = g_part + blockIdx.x * PART_STRIDE;
    float4* P4 = (float4*)Pp;
    for (int idx = tid; idx < KCLS * 16; idx += NTH) {
        int k = idx >> 4, h = idx & 15;
        float4 a = acc4[(k) * 16 + h];          // hw=0
        float4 b = acc4[(129 + k) * 16 + h];    // hw=1
        a.x += b.x; a.y += b.y; a.z += b.z; a.w += b.w;
        P4[k * 16 + h] = a;                      // P[k][64] floats
    }
    if (tid < KCLS) {
        float s = 0.f;
        #pragma unroll
        for (int h = 0; h < 16; h++)
            s += acc2[tid * 16 + h] + acc2[(129 + tid) * 16 + h];
        Pp[8192 + tid] = scnt[tid] + scnt[130 + tid];
        Pp[8320 + tid] = s;
    }
}

// ================= per-class reduction =================
__global__ void __launch_bounds__(256) k_mid() {
    const int k = blockIdx.x;
    const int t = threadIdx.x;
    __shared__ float sred[256];
    __shared__ float wcn[8], wsq[8];
    __shared__ float sc[2];
    __shared__ float sq2r[2];

    const int d = t & 63, g = t >> 6;
    float s = 0.f;
    for (int c = g; c < GRID_MAIN; c += 4)
        s += g_part[c * PART_STRIDE + k * 64 + d];
    sred[t] = s;

    float cn = 0.f, sq = 0.f;
    for (int c = t; c < GRID_MAIN; c += 256) {
        cn += g_part[c * PART_STRIDE + 8192 + k];
        sq += g_part[c * PART_STRIDE + 8320 + k];
    }
    #pragma unroll
    for (int o = 16; o; o >>= 1) {
        cn += __shfl_down_sync(0xffffffffu, cn, o);
        sq += __shfl_down_sync(0xffffffffu, sq, o);
    }
    if ((t & 31) == 0) { wcn[t >> 5] = cn; wsq[t >> 5] = sq; }
    __syncthreads();

    if (t == 0) {
        float c0 = 0.f, s0 = 0.f;
        #pragma unroll
        for (int w = 0; w < 8; w++) { c0 += wcn[w]; s0 += wsq[w]; }
        sc[0] = c0; sc[1] = s0;
    }
    __syncthreads();

    const float cnt = sc[0], ssq = sc[1];
    const float safe = fmaxf(cnt, 1.f);

    float sq2 = 0.f;
    if (t < 64) {
        float sum = sred[t] + sred[t + 64] + sred[t + 128] + sred[t + 192];
        float cd = sum / safe;
        g_centers[k * 64 + t] = cd;
        sq2 = cd * cd;
    }
    #pragma unroll
    for (int o = 16; o; o >>= 1) sq2 += __shfl_down_sync(0xffffffffu, sq2, o);
    if (t == 0)  sq2r[0] = sq2;
    if (t == 32) sq2r[1] = sq2;
    __syncthreads();

    if (t == 0) {
        float sqn = sq2r[0] + sq2r[1];
        g_sqn[k] = sqn;
        g_cntk[k] = cnt;
        float var = ssq / safe - sqn;
        if (cnt > 1.f) { atomicAdd(&g_ivar, var); atomicAdd(&g_nh2, 1.f); }
        if (cnt > 0.f) atomicAdd(&g_nvalid, 1.f);
    }
}

// ================= pairwise distances + final loss =================
__global__ void __launch_bounds__(256) k_pair(float* __restrict__ out) {
    __shared__ float c[KCLS * 65];
    __shared__ float cnts[KCLS];
    __shared__ float sqns[KCLS];
    __shared__ float red[256];

    const int t = threadIdx.x;
    for (int idx = t; idx < KCLS * DDIM; idx += 256)
        c[(idx >> 6) * 65 + (idx & 63)] = g_centers[idx];
    if (t < KCLS) { cnts[t] = g_cntk[t]; sqns[t] = g_sqn[t]; }
    __syncthreads();

    float dsum = 0.f, pcnt = 0.f;
    for (int p = blockIdx.x * 256 + t; p < KCLS * KCLS; p += PAIRBLKS * 256) {
        int i = p >> 7, j = p & 127;
        if (j > i && cnts[i] > 0.f && cnts[j] > 0.f) {
            float d0 = 0.f, d1 = 0.f;
            #pragma unroll
            for (int d = 0; d < DDIM; d += 2) {
                d0 = fmaf(c[i * 65 + d],     c[j * 65 + d],     d0);
                d1 = fmaf(c[i * 65 + d + 1], c[j * 65 + d + 1], d1);
            }
            float sq = sqns[i] + sqns[j] - 2.f * (d0 + d1);
            dsum += sqrtf(fmaxf(sq, 0.f));
            pcnt += 1.f;
        }
    }

    red[t] = dsum; __syncthreads();
    for (int s = 128; s; s >>= 1) { if (t < s) red[t] += red[t + s]; __syncthreads(); }
    if (t == 0) atomicAdd(&g_dsum, red[0]);
    __syncthreads();
    red[t] = pcnt; __syncthreads();
    for (int s = 128; s; s >>= 1) { if (t < s) red[t] += red[t + s]; __syncthreads(); }

    if (t == 0) {
        atomicAdd(&g_pcnt, red[0]);
        __threadfence();
        unsigned tk = atomicAdd(&g_ticket, 1u);
        if (tk == PAIRBLKS - 1) {
            float nh2 = g_nh2, nvalid = g_nvalid, ivar = g_ivar;
            float dT = g_dsum, pT = g_pcnt;
            float intra = (nh2 > 0.f) ? ivar / nh2 : 0.f;
            float inter = (pT > 0.f) ? -dT / pT : 0.f;
            float loss = intra + 0.5f * inter;
            out[0] = (nvalid >= 2.f) ? loss : 0.f;
        }
    }
}

// ================= launch =================
extern "C" void kernel_launch(void* const* d_in, const int* in_sizes, int n_in,
                              void* d_out, int out_size) {
    const float4* z4 = (const float4*)d_in[0];
    const int* labels = (const int*)d_in[1];
    int nrows = in_sizes[0] / DDIM;

    cudaFuncSetAttribute(k_main, cudaFuncAttributeMaxDynamicSharedMemorySize,
                         SMEM_MAIN);

    k_main<<<GRID_MAIN, NTH, SMEM_MAIN>>>(z4, labels, nrows);
    k_mid<<<KCLS, 256>>>();
    k_pair<<<PAIRBLKS, 256>>>((float*)d_out);
}